// round 4
// baseline (speedup 1.0000x reference)
#include <cuda_runtime.h>
#include <math.h>

#define IMG_H 128
#define IMG_W 2048
#define HW    (IMG_H * IMG_W)
#define PAD 3
#define S 7
#define K2 49
#define CENTER 24
#define HP (IMG_H + 2*PAD)   // 134
#define WP2 2064             // padded row stride in elements (mult. of 4, slack for float4 overread)
#define CUTOFF 2.0f

// Device-global scratch (no allocation allowed anywhere)
__device__ float         g_pr[HP * WP2];  // range, zero-padded, invalid -> +inf
__device__ unsigned char g_pa[HP * WP2];  // class, zero-padded
// g_roles: [0] idx of range among HW pair, [1] argmax is 64-bit,
//          [2] idx of unproj among P triple, [3] idx px, [4] idx py,
//          [5] coords/output are 64-bit (jax x64 world)
__device__ int g_roles[6];

struct WParams { float w[K2]; };

// ---------------- role + dtype-width resolution (1 warp) -------------------
__global__ void resolve_kernel(const unsigned* __restrict__ a0,
                               const unsigned* __restrict__ a1,
                               const unsigned* __restrict__ b0,
                               const unsigned* __restrict__ b1,
                               const unsigned* __restrict__ b2)
{
    int lane = threadIdx.x;  // 32 threads

    // HW pair: float range image has large bit patterns; argmax words are 0..19.
    unsigned m0 = __reduce_max_sync(0xffffffffu, (lane < 16) ? a0[lane] : 0u);
    int ir = (m0 > 0x10000u) ? 0 : 1;
    const unsigned* paw = (ir == 0) ? a1 : a0;
    // int64 detection: odd 32-bit words all zero
    unsigned oddA = max(paw[2 * lane + 1], paw[2 * lane + 65]);
    oddA = __reduce_max_sync(0xffffffffu, oddA);
    int a64 = (oddA == 0) ? 1 : 0;

    // P triple: unproj has float bit patterns; coords < 2048 in every word.
    unsigned n0 = __reduce_max_sync(0xffffffffu, (lane < 16) ? b0[lane] : 0u);
    unsigned n1 = __reduce_max_sync(0xffffffffu, (lane < 16) ? b1[lane] : 0u);
    int iu = (n0 > 0x10000u) ? 0 : (n1 > 0x10000u) ? 1 : 2;
    int r0 = (iu == 0) ? 1 : 0;          // remaining two, order preserved
    int r1 = (iu == 2) ? 1 : 2;
    const unsigned* c0 = (r0 == 0) ? b0 : (r0 == 1) ? b1 : b2;
    const unsigned* c1 = (r1 == 0) ? b0 : (r1 == 1) ? b1 : b2;

    unsigned oddC = max(c0[2 * lane + 1], c0[2 * lane + 65]);
    oddC = __reduce_max_sync(0xffffffffu, oddC);
    int w64 = (oddC == 0) ? 1 : 0;

    // px vs py: px has values >= 128 among first 64 (py < 128 always)
    unsigned v0, v1;
    if (w64) {
        v0 = max(c0[4 * lane], c0[4 * lane + 2]);
        v1 = max(c1[4 * lane], c1[4 * lane + 2]);
    } else {
        v0 = max(c0[2 * lane], c0[2 * lane + 1]);
        v1 = max(c1[2 * lane], c1[2 * lane + 1]);
    }
    v0 = __reduce_max_sync(0xffffffffu, v0);
    v1 = __reduce_max_sync(0xffffffffu, v1);
    int ipx = (v0 >= 128u) ? r0 : r1;
    int ipy = (ipx == r0) ? r1 : r0;

    if (lane == 0) {
        g_roles[0] = ir;  g_roles[1] = a64;
        g_roles[2] = iu;  g_roles[3] = ipx;
        g_roles[4] = ipy; g_roles[5] = w64;
    }
}

// ---------------- build padded range(+inf invalid) / class images ----------
__global__ void prep_kernel(const void* __restrict__ A0,
                            const void* __restrict__ A1)
{
    int ir = g_roles[0], a64 = g_roles[1];
    const float* pr_in = (const float*)(ir == 0 ? A0 : A1);
    const void*  pa_in = (ir == 0 ? A1 : A0);

    int idx = blockIdx.x * blockDim.x + threadIdx.x;
    if (idx >= HP * WP2) return;
    int y = idx / WP2, x = idx - y * WP2;
    float v = 0.0f;
    int   c = 0;
    if (y >= PAD && y < IMG_H + PAD && x >= PAD && x < IMG_W + PAD) {
        int src = (y - PAD) * IMG_W + (x - PAD);
        v = pr_in[src];
        c = a64 ? (int)((const long long*)pa_in)[src]
                : ((const int*)pa_in)[src];
    }
    if (v < 0.0f) v = __int_as_float(0x7f800000);  // invalid -> +inf (pad 0 stays 0)
    g_pr[idx] = v;
    g_pa[idx] = (unsigned char)c;
}

// ---------------- main KNN kernel ------------------------------------------
__global__ void __launch_bounds__(256)
knn_kernel(const void* __restrict__ B0,
           const void* __restrict__ B1,
           const void* __restrict__ B2,
           void*       __restrict__ outv,
           int P, WParams wp)
{
    int iu = g_roles[2], ix = g_roles[3], iy = g_roles[4], c64 = g_roles[5];
    const float* unproj = (const float*)(iu == 0 ? B0 : iu == 1 ? B1 : B2);
    const void*  pxv    = (ix == 0 ? B0 : ix == 1 ? B1 : B2);
    const void*  pyv    = (iy == 0 ? B0 : iy == 1 ? B1 : B2);

    int p = blockIdx.x * blockDim.x + threadIdx.x;
    if (p >= P) return;

    float ur = __ldg(&unproj[p]);
    int x, y;
    if (c64) {
        x = (int)((const long long*)pxv)[p];
        y = (int)((const long long*)pyv)[p];
    } else {
        x = ((const int*)pxv)[p];
        y = ((const int*)pyv)[p];
    }

    // patch top-left in padded coords == (y, x); vector base aligned down to 4
    int x0 = x & ~3;
    int a  = x & 3;
    bool s1 = (a & 1) != 0;
    bool s2 = (a & 2) != 0;

    // Fast predicate pass: candidate = (d <= CUTOFF); center (d==0) skipped.
    unsigned long long mask = 0ull;
#pragma unroll
    for (int ky = 0; ky < S; ky++) {
        const float4* rp = (const float4*)(g_pr + (y + ky) * WP2 + x0);
        float4 A = __ldg(rp), B = __ldg(rp + 1), C = __ldg(rp + 2);
        float f[12] = {A.x, A.y, A.z, A.w, B.x, B.y, B.z, B.w, C.x, C.y, C.z, C.w};
        float u[8];
#pragma unroll
        for (int j = 0; j < 8; j++) u[j] = s2 ? f[j + 2] : f[j];
        float v7[7];
#pragma unroll
        for (int j = 0; j < 7; j++) v7[j] = s1 ? u[j + 1] : u[j];
#pragma unroll
        for (int kx = 0; kx < S; kx++) {
            int k = ky * S + kx;
            if (k == CENTER) continue;
            float d = fabsf(v7[kx] - ur) * wp.w[k];
            if (d <= CUTOFF) mask |= (1ull << k);
        }
    }

    unsigned long long votes = 0ull;
    const unsigned char* pa = g_pa + y * WP2 + x;

    if (__popcll(mask) <= 6) {
        // FAST PATH: <=7 candidates incl. center -> all provably in the stable
        // top-7; other top-7 members exceed cutoff -> discarded class slot.
        int cc = (int)__ldg(&pa[PAD * WP2 + PAD]);
        if (cc > 0) votes += 1ull << (3 * cc - 3);
        unsigned long long m = mask;
        while (m) {
            int k = __ffsll((long long)m) - 1;
            m &= m - 1;
            int dy = k / S, dx = k - dy * S;
            int c = (int)__ldg(&pa[dy * WP2 + dx]);
            if (c > 0) votes += 1ull << (3 * c - 3);
        }
    } else {
        // SLOW PATH (~0.3%): exact stable top-7 by repeated strict-< min
        // (strict < == lowest-index tie-break, matching jax.lax.top_k).
        const float* pr = g_pr + y * WP2 + x;
        unsigned long long removed = 0ull;
        for (int r = 0; r < 7; r++) {
            float best = __int_as_float(0x7f800000);
            int   bk   = -1;
            for (int k = 0; k < K2; k++) {
                if ((removed >> k) & 1ull) continue;
                int dy = k / S, dx = k - dy * S;
                float v = (k == CENTER) ? ur : __ldg(&pr[dy * WP2 + dx]);
                float d = fabsf(v - ur) * wp.w[k];
                if (d < best) { best = d; bk = k; }
            }
            removed |= (1ull << bk);
            if (best <= CUTOFF) {
                int dy = bk / S, dx = bk - dy * S;
                int c = (int)__ldg(&pa[dy * WP2 + dx]);
                if (c > 0) votes += 1ull << (3 * c - 3);
            }
        }
    }

    // argmax over classes 1..19 (3-bit counters); ascending + strict '>'
    // == lowest class wins ties; all-zero -> class 1 (argmax(zeros)+1).
    int best_c = 1, best_n = 0;
#pragma unroll
    for (int c = 1; c <= 19; c++) {
        int n = (int)((votes >> (3 * c - 3)) & 7ull);
        if (n > best_n) { best_n = n; best_c = c; }
    }

    if (c64) ((long long*)outv)[p] = (long long)best_c;
    else     ((float*)outv)[p]     = (float)best_c;
}

extern "C" void kernel_launch(void* const* d_in, const int* in_sizes, int n_in,
                              void* d_out, int out_size) {
    // Partition inputs by element count; roles/widths resolved on-device.
    int hw_idx[2], p_idx[3], nh = 0, np_ = 0;
    for (int i = 0; i < n_in; i++) {
        if (in_sizes[i] == HW) { if (nh < 2) hw_idx[nh++] = i; }
        else                   { if (np_ < 3) p_idx[np_++] = i; }
    }
    const void* A0 = d_in[hw_idx[0]];
    const void* A1 = d_in[hw_idx[1]];
    const void* B0 = d_in[p_idx[0]];
    const void* B1 = d_in[p_idx[1]];
    const void* B2 = d_in[p_idx[2]];
    int P = out_size;

    // inv-gaussian weights in float64, exactly like the reference
    WParams wp;
    {
        const double PI = 3.14159265358979323846;
        double g[K2], sum = 0.0;
        double mean = (S - 1) / 2.0;
        for (int yy = 0; yy < S; yy++)
            for (int xx = 0; xx < S; xx++) {
                double dx = xx - mean, dy = yy - mean;
                double e = exp(-(dx * dx + dy * dy) / 2.0) / (2.0 * PI);
                g[yy * S + xx] = e;
                sum += e;
            }
        for (int k = 0; k < K2; k++) wp.w[k] = (float)(1.0 - g[k] / sum);
    }

    resolve_kernel<<<1, 32>>>((const unsigned*)A0, (const unsigned*)A1,
                              (const unsigned*)B0, (const unsigned*)B1,
                              (const unsigned*)B2);
    int npix = HP * WP2;
    prep_kernel<<<(npix + 255) / 256, 256>>>(A0, A1);
    knn_kernel<<<(P + 255) / 256, 256>>>(B0, B1, B2, d_out, P, wp);
}

// round 5
// speedup vs baseline: 1.0935x; 1.0935x over previous
#include <cuda_runtime.h>
#include <math.h>

#define IMG_H 128
#define IMG_W 2048
#define HW    (IMG_H * IMG_W)
#define PAD 3
#define S 7
#define K2 49
#define CENTER 24
#define HP (IMG_H + 2*PAD)   // 134
#define WP2 2064             // padded row stride (elements)
#define CUTOFF 2.0f
#define NBINS (IMG_H * IMG_W)  // 262144 = 256 * 1024
#define NCHUNK 256
#define MAXP  1048576

// ---- device-global scratch (no allocation allowed anywhere) ----
__device__ float         g_pr[HP * WP2];
__device__ unsigned char g_pa[HP * WP2];
__device__ int      g_roles[6];
__device__ unsigned g_hist[NBINS];
__device__ unsigned g_cursor[NBINS];
__device__ unsigned g_bsum[NCHUNK];
__device__ unsigned g_bbase[NCHUNK];
__device__ float    g_ur[MAXP];
__device__ unsigned g_xy[MAXP];
__device__ unsigned g_sidx[MAXP];

struct WParams { float w[K2]; };

// ---------------- role + dtype-width resolution (1 warp) -------------------
__global__ void resolve_kernel(const unsigned* __restrict__ a0,
                               const unsigned* __restrict__ a1,
                               const unsigned* __restrict__ b0,
                               const unsigned* __restrict__ b1,
                               const unsigned* __restrict__ b2)
{
    int lane = threadIdx.x;

    unsigned m0 = __reduce_max_sync(0xffffffffu, (lane < 16) ? a0[lane] : 0u);
    int ir = (m0 > 0x10000u) ? 0 : 1;
    const unsigned* paw = (ir == 0) ? a1 : a0;
    unsigned oddA = max(paw[2 * lane + 1], paw[2 * lane + 65]);
    oddA = __reduce_max_sync(0xffffffffu, oddA);
    int a64 = (oddA == 0) ? 1 : 0;

    unsigned n0 = __reduce_max_sync(0xffffffffu, (lane < 16) ? b0[lane] : 0u);
    unsigned n1 = __reduce_max_sync(0xffffffffu, (lane < 16) ? b1[lane] : 0u);
    int iu = (n0 > 0x10000u) ? 0 : (n1 > 0x10000u) ? 1 : 2;
    int r0 = (iu == 0) ? 1 : 0;
    int r1 = (iu == 2) ? 1 : 2;
    const unsigned* c0 = (r0 == 0) ? b0 : (r0 == 1) ? b1 : b2;
    const unsigned* c1 = (r1 == 0) ? b0 : (r1 == 1) ? b1 : b2;

    unsigned oddC = max(c0[2 * lane + 1], c0[2 * lane + 65]);
    oddC = __reduce_max_sync(0xffffffffu, oddC);
    int w64 = (oddC == 0) ? 1 : 0;

    unsigned v0, v1;
    if (w64) {
        v0 = max(c0[4 * lane], c0[4 * lane + 2]);
        v1 = max(c1[4 * lane], c1[4 * lane + 2]);
    } else {
        v0 = max(c0[2 * lane], c0[2 * lane + 1]);
        v1 = max(c1[2 * lane], c1[2 * lane + 1]);
    }
    v0 = __reduce_max_sync(0xffffffffu, v0);
    v1 = __reduce_max_sync(0xffffffffu, v1);
    int ipx = (v0 >= 128u) ? r0 : r1;
    int ipy = (ipx == r0) ? r1 : r0;

    if (lane == 0) {
        g_roles[0] = ir;  g_roles[1] = a64;
        g_roles[2] = iu;  g_roles[3] = ipx;
        g_roles[4] = ipy; g_roles[5] = w64;
    }
}

// -------- build padded images; also zero the histogram (same pass) ---------
__global__ void prep_kernel(const void* __restrict__ A0,
                            const void* __restrict__ A1)
{
    int idx = blockIdx.x * blockDim.x + threadIdx.x;
    if (idx < NBINS) g_hist[idx] = 0u;
    if (idx >= HP * WP2) return;

    int ir = g_roles[0], a64 = g_roles[1];
    const float* pr_in = (const float*)(ir == 0 ? A0 : A1);
    const void*  pa_in = (ir == 0 ? A1 : A0);

    int y = idx / WP2, x = idx - y * WP2;
    float v = 0.0f;
    int   c = 0;
    if (y >= PAD && y < IMG_H + PAD && x >= PAD && x < IMG_W + PAD) {
        int src = (y - PAD) * IMG_W + (x - PAD);
        v = pr_in[src];
        c = a64 ? (int)((const long long*)pa_in)[src]
                : ((const int*)pa_in)[src];
    }
    if (v < 0.0f) v = __int_as_float(0x7f800000);
    g_pr[idx] = v;
    g_pa[idx] = (unsigned char)c;
}

// ---------------- coordinate fetch helper ----------------------------------
__device__ __forceinline__ void load_xy(const void* pxv, const void* pyv,
                                        int c64, int p, int& x, int& y)
{
    if (c64) {
        x = (int)((const long long*)pxv)[p];
        y = (int)((const long long*)pyv)[p];
    } else {
        x = ((const int*)pxv)[p];
        y = ((const int*)pyv)[p];
    }
}

// ---------------- histogram over pixel bins --------------------------------
__global__ void hist_kernel(const void* __restrict__ B0,
                            const void* __restrict__ B1,
                            const void* __restrict__ B2, int P)
{
    int p = blockIdx.x * blockDim.x + threadIdx.x;
    if (p >= P) return;
    int ix = g_roles[3], iy = g_roles[4], c64 = g_roles[5];
    const void* pxv = (ix == 0 ? B0 : ix == 1 ? B1 : B2);
    const void* pyv = (iy == 0 ? B0 : iy == 1 ? B1 : B2);
    int x, y; load_xy(pxv, pyv, c64, p, x, y);
    atomicAdd(&g_hist[y * IMG_W + x], 1u);
}

// ---------------- 3-phase exclusive scan over 256K bins --------------------
__global__ void __launch_bounds__(1024) scan1_kernel() {
    int i = blockIdx.x * 1024 + threadIdx.x;
    unsigned v = g_hist[i];
    unsigned inc = v;
#pragma unroll
    for (int o = 1; o < 32; o <<= 1) {
        unsigned n = __shfl_up_sync(0xffffffffu, inc, o);
        if ((threadIdx.x & 31) >= o) inc += n;
    }
    __shared__ unsigned ws[32];
    if ((threadIdx.x & 31) == 31) ws[threadIdx.x >> 5] = inc;
    __syncthreads();
    if (threadIdx.x < 32) {
        unsigned wv = ws[threadIdx.x];
        unsigned wi = wv;
#pragma unroll
        for (int o = 1; o < 32; o <<= 1) {
            unsigned n = __shfl_up_sync(0xffffffffu, wi, o);
            if (threadIdx.x >= o) wi += n;
        }
        ws[threadIdx.x] = wi - wv;                 // exclusive warp offset
        if (threadIdx.x == 31) g_bsum[blockIdx.x] = wi;
    }
    __syncthreads();
    g_cursor[i] = (inc - v) + ws[threadIdx.x >> 5];  // block-exclusive
}

__global__ void scan2_kernel() {   // 1 block, 256 threads
    unsigned v = g_bsum[threadIdx.x];
    unsigned inc = v;
#pragma unroll
    for (int o = 1; o < 32; o <<= 1) {
        unsigned n = __shfl_up_sync(0xffffffffu, inc, o);
        if ((threadIdx.x & 31) >= o) inc += n;
    }
    __shared__ unsigned ws[8];
    if ((threadIdx.x & 31) == 31) ws[threadIdx.x >> 5] = inc;
    __syncthreads();
    if (threadIdx.x < 8) {
        unsigned wv = ws[threadIdx.x];
        unsigned wi = wv;
#pragma unroll
        for (int o = 1; o < 8; o <<= 1) {
            unsigned n = __shfl_up_sync(0xffu, wi, o);
            if (threadIdx.x >= o) wi += n;
        }
        ws[threadIdx.x] = wi - wv;
    }
    __syncthreads();
    g_bbase[threadIdx.x] = (inc - v) + ws[threadIdx.x >> 5];
}

__global__ void scan3_kernel() {
    int i = blockIdx.x * blockDim.x + threadIdx.x;
    g_cursor[i] += g_bbase[i >> 10];
}

// ---------------- scatter points into pixel-sorted order -------------------
__global__ void scatter_kernel(const void* __restrict__ B0,
                               const void* __restrict__ B1,
                               const void* __restrict__ B2, int P)
{
    int p = blockIdx.x * blockDim.x + threadIdx.x;
    if (p >= P) return;
    int iu = g_roles[2], ix = g_roles[3], iy = g_roles[4], c64 = g_roles[5];
    const float* unproj = (const float*)(iu == 0 ? B0 : iu == 1 ? B1 : B2);
    const void*  pxv    = (ix == 0 ? B0 : ix == 1 ? B1 : B2);
    const void*  pyv    = (iy == 0 ? B0 : iy == 1 ? B1 : B2);
    int x, y; load_xy(pxv, pyv, c64, p, x, y);
    unsigned pos = atomicAdd(&g_cursor[y * IMG_W + x], 1u);
    g_ur[pos]   = __ldg(&unproj[p]);
    g_xy[pos]   = ((unsigned)y << 16) | (unsigned)x;
    g_sidx[pos] = (unsigned)p;
}

// ---------------- main KNN kernel (pixel-sorted order) ---------------------
__global__ void __launch_bounds__(256)
knn_kernel(void* __restrict__ outv, int P, WParams wp)
{
    int i = blockIdx.x * blockDim.x + threadIdx.x;
    if (i >= P) return;

    float    ur = g_ur[i];
    unsigned xy = g_xy[i];
    int x = (int)(xy & 0xffffu);
    int y = (int)(xy >> 16);

    int base = y * WP2 + x;          // patch top-left in padded coords
    const float*         pr = g_pr + base;
    const unsigned char* pa = g_pa + base;

    // Fast predicate pass: candidate = (d <= CUTOFF); center (d==0) skipped.
    unsigned long long mask = 0ull;
#pragma unroll
    for (int ky = 0; ky < S; ky++) {
#pragma unroll
        for (int kx = 0; kx < S; kx++) {
            int k = ky * S + kx;
            if (k == CENTER) continue;
            float v = __ldg(&pr[ky * WP2 + kx]);
            float d = fabsf(v - ur) * wp.w[k];
            if (d <= CUTOFF) mask |= (1ull << k);
        }
    }

    unsigned long long votes = 0ull;

    if (__popcll(mask) <= 6) {
        // FAST PATH: <=7 candidates incl. center -> all provably in the stable
        // top-7; remaining top-7 members exceed cutoff -> discarded class slot.
        int cc = (int)__ldg(&pa[PAD * WP2 + PAD]);
        if (cc > 0) votes += 1ull << (3 * cc - 3);
        unsigned long long m = mask;
        while (m) {
            int k = __ffsll((long long)m) - 1;
            m &= m - 1;
            int dy = k / S, dx = k - dy * S;
            int c = (int)__ldg(&pa[dy * WP2 + dx]);
            if (c > 0) votes += 1ull << (3 * c - 3);
        }
    } else {
        // SLOW PATH (~0.3%): exact stable top-7 by repeated strict-< min
        // (strict < == lowest-index tie-break, matching jax.lax.top_k).
        unsigned long long removed = 0ull;
        for (int r = 0; r < 7; r++) {
            float best = __int_as_float(0x7f800000);
            int   bk   = -1;
            for (int k = 0; k < K2; k++) {
                if ((removed >> k) & 1ull) continue;
                int dy = k / S, dx = k - dy * S;
                float v = (k == CENTER) ? ur : __ldg(&pr[dy * WP2 + dx]);
                float d = fabsf(v - ur) * wp.w[k];
                if (d < best) { best = d; bk = k; }
            }
            removed |= (1ull << bk);
            if (best <= CUTOFF) {
                int dy = bk / S, dx = bk - dy * S;
                int c = (int)__ldg(&pa[dy * WP2 + dx]);
                if (c > 0) votes += 1ull << (3 * c - 3);
            }
        }
    }

    // argmax over classes 1..19 (3-bit counters); strict '>' == lowest class
    // wins ties; all-zero -> class 1 (argmax(zeros)+1).
    int best_c = 1, best_n = 0;
#pragma unroll
    for (int c = 1; c <= 19; c++) {
        int n = (int)((votes >> (3 * c - 3)) & 7ull);
        if (n > best_n) { best_n = n; best_c = c; }
    }

    unsigned op = g_sidx[i];
    if (g_roles[5]) ((long long*)outv)[op] = (long long)best_c;
    else            ((float*)outv)[op]     = (float)best_c;
}

extern "C" void kernel_launch(void* const* d_in, const int* in_sizes, int n_in,
                              void* d_out, int out_size) {
    int hw_idx[2], p_idx[3], nh = 0, np_ = 0;
    for (int i = 0; i < n_in; i++) {
        if (in_sizes[i] == HW) { if (nh < 2) hw_idx[nh++] = i; }
        else                   { if (np_ < 3) p_idx[np_++] = i; }
    }
    const void* A0 = d_in[hw_idx[0]];
    const void* A1 = d_in[hw_idx[1]];
    const void* B0 = d_in[p_idx[0]];
    const void* B1 = d_in[p_idx[1]];
    const void* B2 = d_in[p_idx[2]];
    int P = out_size;

    WParams wp;
    {
        const double PI = 3.14159265358979323846;
        double g[K2], sum = 0.0;
        double mean = (S - 1) / 2.0;
        for (int yy = 0; yy < S; yy++)
            for (int xx = 0; xx < S; xx++) {
                double dx = xx - mean, dy = yy - mean;
                double e = exp(-(dx * dx + dy * dy) / 2.0) / (2.0 * PI);
                g[yy * S + xx] = e;
                sum += e;
            }
        for (int k = 0; k < K2; k++) wp.w[k] = (float)(1.0 - g[k] / sum);
    }

    resolve_kernel<<<1, 32>>>((const unsigned*)A0, (const unsigned*)A1,
                              (const unsigned*)B0, (const unsigned*)B1,
                              (const unsigned*)B2);
    int npix = HP * WP2;
    prep_kernel<<<(npix + 255) / 256, 256>>>(A0, A1);
    hist_kernel<<<(P + 255) / 256, 256>>>(B0, B1, B2, P);
    scan1_kernel<<<NCHUNK, 1024>>>();
    scan2_kernel<<<1, 256>>>();
    scan3_kernel<<<NBINS / 256, 256>>>();
    scatter_kernel<<<(P + 255) / 256, 256>>>(B0, B1, B2, P);
    knn_kernel<<<(P + 255) / 256, 256>>>(d_out, P, wp);
}

// round 6
// speedup vs baseline: 2.3583x; 2.1566x over previous
#include <cuda_runtime.h>
#include <math.h>

#define IMG_H 128
#define IMG_W 2048
#define HW    (IMG_H * IMG_W)
#define PAD 3
#define S 7
#define K2 49
#define CENTER 24
#define HP (IMG_H + 2*PAD)   // 134
#define WP2 2064             // padded row stride (elements)
#define CUTOFF 2.0f
#define NBINS (IMG_H * IMG_W)  // 262144 = 256 * 1024
#define NCHUNK 256
#define MAXP  1048576

// ---- device-global scratch (no allocation allowed anywhere) ----
__device__ float         g_pr[HP * WP2];
__device__ unsigned char g_pa[HP * WP2];
__device__ int      g_roles[6];
__device__ unsigned g_hist[NBINS];
__device__ unsigned g_cursor[NBINS];
__device__ unsigned g_bsum[NCHUNK];
__device__ unsigned g_bbase[NCHUNK];
__device__ unsigned g_ctr;
__device__ uint4    g_pay[MAXP];     // {ur_bits, (y<<16)|x, orig_idx, 0}

struct WParams { float w[K2]; };
struct Roles { int ir, a64, iu, ipx, ipy, w64; };

// ---------------- role + dtype detection (scalar, ~400 L2-hot loads) -------
__device__ Roles compute_roles(const unsigned* a0, const unsigned* a1,
                               const unsigned* b0, const unsigned* b1,
                               const unsigned* b2)
{
    Roles R;
    unsigned m0 = 0;
    for (int i = 0; i < 16; i++) m0 = max(m0, a0[i]);
    R.ir = (m0 > 0x10000u) ? 0 : 1;                 // float range image
    const unsigned* paw = (R.ir == 0) ? a1 : a0;
    unsigned oddA = 0;
    for (int i = 1; i < 128; i += 2) oddA = max(oddA, paw[i]);
    R.a64 = (oddA == 0);                            // int64: high words all 0

    unsigned n0 = 0, n1 = 0;
    for (int i = 0; i < 16; i++) { n0 = max(n0, b0[i]); n1 = max(n1, b1[i]); }
    R.iu = (n0 > 0x10000u) ? 0 : (n1 > 0x10000u) ? 1 : 2;
    int r0 = (R.iu == 0) ? 1 : 0;
    int r1 = (R.iu == 2) ? 1 : 2;
    const unsigned* c0 = (r0 == 0) ? b0 : (r0 == 1) ? b1 : b2;
    const unsigned* c1 = (r1 == 0) ? b0 : (r1 == 1) ? b1 : b2;
    unsigned oddC = 0;
    for (int i = 1; i < 128; i += 2) oddC = max(oddC, c0[i]);
    R.w64 = (oddC == 0);

    unsigned v0 = 0, v1 = 0;
    if (R.w64) {
        for (int i = 0; i < 64; i++) { v0 = max(v0, c0[2 * i]); v1 = max(v1, c1[2 * i]); }
    } else {
        for (int i = 0; i < 64; i++) { v0 = max(v0, c0[i]); v1 = max(v1, c1[i]); }
    }
    R.ipx = (v0 >= 128u) ? r0 : r1;   // px has values >= 128 w.h.p.
    R.ipy = (R.ipx == r0) ? r1 : r0;
    return R;
}

// -------- prep: roles, padded images, zero hist + chunk counter ------------
__global__ void prep_kernel(const void* __restrict__ A0,
                            const void* __restrict__ A1,
                            const void* __restrict__ B0,
                            const void* __restrict__ B1,
                            const void* __restrict__ B2)
{
    __shared__ Roles Rs;
    if (threadIdx.x == 0) {
        Rs = compute_roles((const unsigned*)A0, (const unsigned*)A1,
                           (const unsigned*)B0, (const unsigned*)B1,
                           (const unsigned*)B2);
        if (blockIdx.x == 0) {
            g_roles[0] = Rs.ir;  g_roles[1] = Rs.a64;
            g_roles[2] = Rs.iu;  g_roles[3] = Rs.ipx;
            g_roles[4] = Rs.ipy; g_roles[5] = Rs.w64;
            g_ctr = 0u;
        }
    }
    __syncthreads();

    int idx = blockIdx.x * blockDim.x + threadIdx.x;
    if (idx < NBINS) g_hist[idx] = 0u;
    if (idx >= HP * WP2) return;

    const float* pr_in = (const float*)(Rs.ir == 0 ? A0 : A1);
    const void*  pa_in = (Rs.ir == 0 ? A1 : A0);

    int y = idx / WP2, x = idx - y * WP2;
    float v = 0.0f;
    int   c = 0;
    if (y >= PAD && y < IMG_H + PAD && x >= PAD && x < IMG_W + PAD) {
        int src = (y - PAD) * IMG_W + (x - PAD);
        v = pr_in[src];
        c = Rs.a64 ? (int)((const long long*)pa_in)[src]
                   : ((const int*)pa_in)[src];
    }
    if (v < 0.0f) v = __int_as_float(0x7f800000);  // invalid -> +inf
    g_pr[idx] = v;
    g_pa[idx] = (unsigned char)c;
}

__device__ __forceinline__ void load_xy(const void* pxv, const void* pyv,
                                        int c64, int p, int& x, int& y)
{
    if (c64) {
        x = (int)((const long long*)pxv)[p];
        y = (int)((const long long*)pyv)[p];
    } else {
        x = ((const int*)pxv)[p];
        y = ((const int*)pyv)[p];
    }
}

// ---------------- histogram over pixel bins --------------------------------
__global__ void hist_kernel(const void* __restrict__ B0,
                            const void* __restrict__ B1,
                            const void* __restrict__ B2, int P)
{
    int p = blockIdx.x * blockDim.x + threadIdx.x;
    if (p >= P) return;
    int ix = g_roles[3], iy = g_roles[4], c64 = g_roles[5];
    const void* pxv = (ix == 0 ? B0 : ix == 1 ? B1 : B2);
    const void* pyv = (iy == 0 ? B0 : iy == 1 ? B1 : B2);
    int x, y; load_xy(pxv, pyv, c64, p, x, y);
    atomicAdd(&g_hist[y * IMG_W + x], 1u);
}

// -------- scan: block-exclusive into cursor; last block scans chunk sums ---
__global__ void __launch_bounds__(1024) scan_kernel() {
    int i = blockIdx.x * 1024 + threadIdx.x;
    unsigned v = g_hist[i];
    unsigned inc = v;
#pragma unroll
    for (int o = 1; o < 32; o <<= 1) {
        unsigned n = __shfl_up_sync(0xffffffffu, inc, o);
        if ((threadIdx.x & 31) >= o) inc += n;
    }
    __shared__ unsigned ws[32];
    if ((threadIdx.x & 31) == 31) ws[threadIdx.x >> 5] = inc;
    __syncthreads();
    if (threadIdx.x < 32) {
        unsigned wv = ws[threadIdx.x];
        unsigned wi = wv;
#pragma unroll
        for (int o = 1; o < 32; o <<= 1) {
            unsigned n = __shfl_up_sync(0xffffffffu, wi, o);
            if (threadIdx.x >= o) wi += n;
        }
        ws[threadIdx.x] = wi - wv;
        if (threadIdx.x == 31) g_bsum[blockIdx.x] = wi;
    }
    __syncthreads();
    g_cursor[i] = (inc - v) + ws[threadIdx.x >> 5];  // block-exclusive

    // decoupled chunk scan: last-arriving block scans g_bsum -> g_bbase
    __threadfence();
    __shared__ int lastf;
    if (threadIdx.x == 0) lastf = (atomicAdd(&g_ctr, 1u) == NCHUNK - 1);
    __syncthreads();
    if (lastf && threadIdx.x < NCHUNK) {
        unsigned bv = g_bsum[threadIdx.x];
        unsigned binc = bv;
#pragma unroll
        for (int o = 1; o < 32; o <<= 1) {
            unsigned n = __shfl_up_sync(0xffffffffu, binc, o);
            if ((threadIdx.x & 31) >= o) binc += n;
        }
        __shared__ unsigned ws2[8];
        if ((threadIdx.x & 31) == 31) ws2[threadIdx.x >> 5] = binc;
        __syncwarp();
        asm volatile("bar.sync 1, 256;" ::: "memory");
        unsigned wo = 0;
        for (int j = 0; j < (threadIdx.x >> 5); j++) wo += ws2[j];
        g_bbase[threadIdx.x] = (binc - bv) + wo;
    }
}

// ---------------- scatter points into pixel-sorted order -------------------
__global__ void scatter_kernel(const void* __restrict__ B0,
                               const void* __restrict__ B1,
                               const void* __restrict__ B2, int P)
{
    int p = blockIdx.x * blockDim.x + threadIdx.x;
    if (p >= P) return;
    int iu = g_roles[2], ix = g_roles[3], iy = g_roles[4], c64 = g_roles[5];
    const float* unproj = (const float*)(iu == 0 ? B0 : iu == 1 ? B1 : B2);
    const void*  pxv    = (ix == 0 ? B0 : ix == 1 ? B1 : B2);
    const void*  pyv    = (iy == 0 ? B0 : iy == 1 ? B1 : B2);
    int x, y; load_xy(pxv, pyv, c64, p, x, y);
    int bin = y * IMG_W + x;
    unsigned pos = atomicAdd(&g_cursor[bin], 1u) + g_bbase[bin >> 10];
    g_pay[pos] = make_uint4(__float_as_uint(__ldg(&unproj[p])),
                            ((unsigned)y << 16) | (unsigned)x,
                            (unsigned)p, 0u);
}

// ---------------- main KNN kernel (pixel-sorted order) ---------------------
__global__ void __launch_bounds__(256)
knn_kernel(void* __restrict__ outv, int P, WParams wp)
{
    int i = blockIdx.x * blockDim.x + threadIdx.x;
    if (i >= P) return;

    uint4 pay = g_pay[i];
    float ur = __uint_as_float(pay.x);
    int x = (int)(pay.y & 0xffffu);
    int y = (int)(pay.y >> 16);

    int base = y * WP2 + x;          // patch top-left in padded coords
    const float*         pr = g_pr + base;
    const unsigned char* pa = g_pa + base;

    // Fast predicate pass: candidate = (d <= CUTOFF); center (d==0) skipped.
    unsigned long long mask = 0ull;
#pragma unroll
    for (int ky = 0; ky < S; ky++) {
#pragma unroll
        for (int kx = 0; kx < S; kx++) {
            int k = ky * S + kx;
            if (k == CENTER) continue;
            float v = __ldg(&pr[ky * WP2 + kx]);
            float d = fabsf(v - ur) * wp.w[k];
            if (d <= CUTOFF) mask |= (1ull << k);
        }
    }

    unsigned long long votes = 0ull;

    if (__popcll(mask) <= 6) {
        // FAST PATH: <=7 candidates incl. center -> all provably in the stable
        // top-7; remaining top-7 members exceed cutoff -> discarded class slot.
        int cc = (int)__ldg(&pa[PAD * WP2 + PAD]);
        if (cc > 0) votes += 1ull << (3 * cc - 3);
        unsigned long long m = mask;
        while (m) {
            int k = __ffsll((long long)m) - 1;
            m &= m - 1;
            int dy = k / S, dx = k - dy * S;
            int c = (int)__ldg(&pa[dy * WP2 + dx]);
            if (c > 0) votes += 1ull << (3 * c - 3);
        }
    } else {
        // SLOW PATH (~1%): C>=8 candidates (all d<=CUTOFF, every non-candidate
        // d>CUTOFF) -> the stable top-7 are the 7 smallest candidates.
        // Key = (f32bits(d) << 6) | k : monotone in d (d>=0), lowest-k ties —
        // exactly jax.lax.top_k's stable order. Insertion into 7 sorted regs.
        unsigned long long cand = mask | (1ull << CENTER);
        unsigned long long t0 = ~0ull, t1 = ~0ull, t2 = ~0ull, t3 = ~0ull,
                           t4 = ~0ull, t5 = ~0ull, t6 = ~0ull;
        while (cand) {
            int k = __ffsll((long long)cand) - 1;
            cand &= cand - 1;
            int dy = k / S, dx = k - dy * S;
            float v = (k == CENTER) ? ur : __ldg(&pr[dy * WP2 + dx]);
            float d = fabsf(v - ur) * wp.w[k];
            unsigned long long key =
                ((unsigned long long)__float_as_uint(d) << 6) | (unsigned)k;
            if (key < t6) {
                t6 = key;
                if (t6 < t5) { unsigned long long s = t5; t5 = t6; t6 = s; }
                if (t5 < t4) { unsigned long long s = t4; t4 = t5; t5 = s; }
                if (t4 < t3) { unsigned long long s = t3; t3 = t4; t4 = s; }
                if (t3 < t2) { unsigned long long s = t2; t2 = t3; t3 = s; }
                if (t2 < t1) { unsigned long long s = t1; t1 = t2; t2 = s; }
                if (t1 < t0) { unsigned long long s = t0; t0 = t1; t1 = s; }
            }
        }
        // all 7 slots filled (C>=8) and all selected d <= CUTOFF: vote each.
        unsigned long long ts[7] = {t0, t1, t2, t3, t4, t5, t6};
#pragma unroll
        for (int j = 0; j < 7; j++) {
            int k = (int)(ts[j] & 63ull);
            int dy = k / S, dx = k - dy * S;
            int c = (int)__ldg(&pa[dy * WP2 + dx]);
            if (c > 0) votes += 1ull << (3 * c - 3);
        }
    }

    // argmax over classes 1..19 (3-bit counters); strict '>' == lowest class
    // wins ties; all-zero -> class 1 (argmax(zeros)+1).
    int best_c = 1, best_n = 0;
#pragma unroll
    for (int c = 1; c <= 19; c++) {
        int n = (int)((votes >> (3 * c - 3)) & 7ull);
        if (n > best_n) { best_n = n; best_c = c; }
    }

    unsigned op = pay.z;
    if (g_roles[5]) ((long long*)outv)[op] = (long long)best_c;
    else            ((float*)outv)[op]     = (float)best_c;
}

extern "C" void kernel_launch(void* const* d_in, const int* in_sizes, int n_in,
                              void* d_out, int out_size) {
    int hw_idx[2], p_idx[3], nh = 0, np_ = 0;
    for (int i = 0; i < n_in; i++) {
        if (in_sizes[i] == HW) { if (nh < 2) hw_idx[nh++] = i; }
        else                   { if (np_ < 3) p_idx[np_++] = i; }
    }
    const void* A0 = d_in[hw_idx[0]];
    const void* A1 = d_in[hw_idx[1]];
    const void* B0 = d_in[p_idx[0]];
    const void* B1 = d_in[p_idx[1]];
    const void* B2 = d_in[p_idx[2]];
    int P = out_size;

    WParams wp;
    {
        const double PI = 3.14159265358979323846;
        double g[K2], sum = 0.0;
        double mean = (S - 1) / 2.0;
        for (int yy = 0; yy < S; yy++)
            for (int xx = 0; xx < S; xx++) {
                double dx = xx - mean, dy = yy - mean;
                double e = exp(-(dx * dx + dy * dy) / 2.0) / (2.0 * PI);
                g[yy * S + xx] = e;
                sum += e;
            }
        for (int k = 0; k < K2; k++) wp.w[k] = (float)(1.0 - g[k] / sum);
    }

    int npix = HP * WP2;
    prep_kernel<<<(npix + 255) / 256, 256>>>(A0, A1, B0, B1, B2);
    hist_kernel<<<(P + 255) / 256, 256>>>(B0, B1, B2, P);
    scan_kernel<<<NCHUNK, 1024>>>();
    scatter_kernel<<<(P + 255) / 256, 256>>>(B0, B1, B2, P);
    knn_kernel<<<(P + 255) / 256, 256>>>(d_out, P, wp);
}

// round 9
// speedup vs baseline: 2.3594x; 1.0004x over previous
#include <cuda_runtime.h>
#include <math.h>

#define IMG_H 128
#define IMG_W 2048
#define HW    (IMG_H * IMG_W)
#define PAD 3
#define S 7
#define K2 49
#define CENTER 24
#define HP (IMG_H + 2*PAD)   // 134
#define WP2 2064             // padded row stride (elements)
#define CUTOFF 2.0f
#define NBINS (IMG_H * IMG_W)  // 262144 = 256 * 1024
#define NCHUNK 256
#define MAXP  1048576

// ---- device-global scratch (no allocation allowed anywhere) ----
__device__ float         g_pr[HP * WP2];
__device__ unsigned char g_pa[HP * WP2];
__device__ int      g_roles[6];
__device__ unsigned g_hist[NBINS];
__device__ unsigned g_cursor[NBINS];
__device__ unsigned g_bsum[NCHUNK];
__device__ unsigned g_bbase[NCHUNK];
__device__ unsigned g_ctr;
__device__ unsigned g_bin[MAXP];     // cached bin index per point
__device__ uint4    g_pay[MAXP];     // {ur_bits, (y<<16)|x, orig_idx, 0}

struct WParams { float w[K2]; };
struct Roles { int ir, a64, iu, ipx, ipy, w64; };

// ---------------- role + dtype detection (scalar, L2-hot loads) ------------
__device__ Roles compute_roles(const unsigned* a0, const unsigned* a1,
                               const unsigned* b0, const unsigned* b1,
                               const unsigned* b2)
{
    Roles R;
    unsigned m0 = 0;
    for (int i = 0; i < 16; i++) m0 = max(m0, a0[i]);
    R.ir = (m0 > 0x10000u) ? 0 : 1;                 // float range image
    const unsigned* paw = (R.ir == 0) ? a1 : a0;
    unsigned oddA = 0;
    for (int i = 1; i < 128; i += 2) oddA = max(oddA, paw[i]);
    R.a64 = (oddA == 0);                            // int64: high words all 0

    unsigned n0 = 0, n1 = 0;
    for (int i = 0; i < 16; i++) { n0 = max(n0, b0[i]); n1 = max(n1, b1[i]); }
    R.iu = (n0 > 0x10000u) ? 0 : (n1 > 0x10000u) ? 1 : 2;
    int r0 = (R.iu == 0) ? 1 : 0;
    int r1 = (R.iu == 2) ? 1 : 2;
    const unsigned* c0 = (r0 == 0) ? b0 : (r0 == 1) ? b1 : b2;
    const unsigned* c1 = (r1 == 0) ? b0 : (r1 == 1) ? b1 : b2;
    unsigned oddC = 0;
    for (int i = 1; i < 128; i += 2) oddC = max(oddC, c0[i]);
    R.w64 = (oddC == 0);

    unsigned v0 = 0, v1 = 0;
    if (R.w64) {
        for (int i = 0; i < 64; i++) { v0 = max(v0, c0[2 * i]); v1 = max(v1, c1[2 * i]); }
    } else {
        for (int i = 0; i < 64; i++) { v0 = max(v0, c0[i]); v1 = max(v1, c1[i]); }
    }
    R.ipx = (v0 >= 128u) ? r0 : r1;   // px has values >= 128 w.h.p.
    R.ipy = (R.ipx == r0) ? r1 : r0;
    return R;
}

// -------- prep: roles, padded images, zero hist + scan counter -------------
__global__ void prep_kernel(const void* __restrict__ A0,
                            const void* __restrict__ A1,
                            const void* __restrict__ B0,
                            const void* __restrict__ B1,
                            const void* __restrict__ B2)
{
    __shared__ Roles Rs;
    if (threadIdx.x == 0) {
        Rs = compute_roles((const unsigned*)A0, (const unsigned*)A1,
                           (const unsigned*)B0, (const unsigned*)B1,
                           (const unsigned*)B2);
        if (blockIdx.x == 0) {
            g_roles[0] = Rs.ir;  g_roles[1] = Rs.a64;
            g_roles[2] = Rs.iu;  g_roles[3] = Rs.ipx;
            g_roles[4] = Rs.ipy; g_roles[5] = Rs.w64;
            g_ctr = 0u;
        }
    }
    __syncthreads();

    int idx = blockIdx.x * blockDim.x + threadIdx.x;
    if (idx < NBINS) g_hist[idx] = 0u;
    if (idx >= HP * WP2) return;

    const float* pr_in = (const float*)(Rs.ir == 0 ? A0 : A1);
    const void*  pa_in = (Rs.ir == 0 ? A1 : A0);

    int y = idx / WP2, x = idx - y * WP2;
    float v = 0.0f;
    int   c = 0;
    if (y >= PAD && y < IMG_H + PAD && x >= PAD && x < IMG_W + PAD) {
        int src = (y - PAD) * IMG_W + (x - PAD);
        v = pr_in[src];
        c = Rs.a64 ? (int)((const long long*)pa_in)[src]
                   : ((const int*)pa_in)[src];
    }
    if (v < 0.0f) v = __int_as_float(0x7f800000);  // invalid -> +inf
    g_pr[idx] = v;
    g_pa[idx] = (unsigned char)c;
}

// -------- histogram: read coords ONCE, cache bin for scatter ---------------
__global__ void hist_kernel(const void* __restrict__ B0,
                            const void* __restrict__ B1,
                            const void* __restrict__ B2, int P)
{
    int p = blockIdx.x * blockDim.x + threadIdx.x;
    if (p >= P) return;
    int ix = g_roles[3], iy = g_roles[4], c64 = g_roles[5];
    const void* pxv = (ix == 0 ? B0 : ix == 1 ? B1 : B2);
    const void* pyv = (iy == 0 ? B0 : iy == 1 ? B1 : B2);
    int x, y;
    if (c64) {
        x = (int)((const long long*)pxv)[p];
        y = (int)((const long long*)pyv)[p];
    } else {
        x = ((const int*)pxv)[p];
        y = ((const int*)pyv)[p];
    }
    unsigned bin = (unsigned)(y * IMG_W + x);
    g_bin[p] = bin;
    atomicAdd(&g_hist[bin], 1u);
}

// -------- scan: block-exclusive into cursor; last block scans chunk sums ---
__global__ void __launch_bounds__(1024) scan_kernel() {
    int i = blockIdx.x * 1024 + threadIdx.x;
    unsigned v = g_hist[i];
    unsigned inc = v;
#pragma unroll
    for (int o = 1; o < 32; o <<= 1) {
        unsigned n = __shfl_up_sync(0xffffffffu, inc, o);
        if ((threadIdx.x & 31) >= o) inc += n;
    }
    __shared__ unsigned ws[32];
    if ((threadIdx.x & 31) == 31) ws[threadIdx.x >> 5] = inc;
    __syncthreads();
    if (threadIdx.x < 32) {
        unsigned wv = ws[threadIdx.x];
        unsigned wi = wv;
#pragma unroll
        for (int o = 1; o < 32; o <<= 1) {
            unsigned n = __shfl_up_sync(0xffffffffu, wi, o);
            if (threadIdx.x >= o) wi += n;
        }
        ws[threadIdx.x] = wi - wv;
        if (threadIdx.x == 31) g_bsum[blockIdx.x] = wi;
    }
    __syncthreads();
    g_cursor[i] = (inc - v) + ws[threadIdx.x >> 5];  // block-exclusive

    // decoupled chunk scan: last-arriving block scans g_bsum -> g_bbase
    // (g_ctr was reset to 0 by prep_kernel block 0 in this same sequence)
    __threadfence();
    __shared__ int lastf;
    if (threadIdx.x == 0) lastf = (atomicAdd(&g_ctr, 1u) == NCHUNK - 1);
    __syncthreads();
    if (lastf && threadIdx.x < NCHUNK) {
        unsigned bv = g_bsum[threadIdx.x];
        unsigned binc = bv;
#pragma unroll
        for (int o = 1; o < 32; o <<= 1) {
            unsigned n = __shfl_up_sync(0xffffffffu, binc, o);
            if ((threadIdx.x & 31) >= o) binc += n;
        }
        __shared__ unsigned ws2[8];
        if ((threadIdx.x & 31) == 31) ws2[threadIdx.x >> 5] = binc;
        __syncwarp();
        asm volatile("bar.sync 1, 256;" ::: "memory");
        unsigned wo = 0;
        for (int j = 0; j < (threadIdx.x >> 5); j++) wo += ws2[j];
        g_bbase[threadIdx.x] = (binc - bv) + wo;
    }
}

// ---------------- scatter points into pixel-sorted order -------------------
__global__ void scatter_kernel(const void* __restrict__ B0,
                               const void* __restrict__ B1,
                               const void* __restrict__ B2, int P)
{
    int p = blockIdx.x * blockDim.x + threadIdx.x;
    if (p >= P) return;
    int iu = g_roles[2];
    const float* unproj = (const float*)(iu == 0 ? B0 : iu == 1 ? B1 : B2);
    unsigned bin = g_bin[p];                  // coalesced u32, no coord re-read
    unsigned x = bin & (IMG_W - 1);
    unsigned y = bin >> 11;
    unsigned pos = atomicAdd(&g_cursor[bin], 1u) + g_bbase[bin >> 10];
    g_pay[pos] = make_uint4(__float_as_uint(__ldg(&unproj[p])),
                            (y << 16) | x, (unsigned)p, 0u);
}

// ---------------- main KNN kernel (pixel-sorted order) ---------------------
__global__ void __launch_bounds__(256)
knn_kernel(void* __restrict__ outv, int P, WParams wp)
{
    int i = blockIdx.x * blockDim.x + threadIdx.x;
    if (i >= P) return;

    uint4 pay = g_pay[i];
    float ur = __uint_as_float(pay.x);
    int x = (int)(pay.y & 0xffffu);
    int y = (int)(pay.y >> 16);

    int base = y * WP2 + x;          // patch top-left in padded coords
    const float*         pr = g_pr + base;
    const unsigned char* pa = g_pa + base;

    // Fast predicate pass: candidate = (d <= CUTOFF); center (d==0) skipped.
    unsigned long long mask = 0ull;
#pragma unroll
    for (int ky = 0; ky < S; ky++) {
#pragma unroll
        for (int kx = 0; kx < S; kx++) {
            int k = ky * S + kx;
            if (k == CENTER) continue;
            float v = __ldg(&pr[ky * WP2 + kx]);
            float d = fabsf(v - ur) * wp.w[k];
            if (d <= CUTOFF) mask |= (1ull << k);
        }
    }

    unsigned long long votes = 0ull;

    if (__popcll(mask) <= 6) {
        // FAST PATH: <=7 candidates incl. center -> all provably in the stable
        // top-7; remaining top-7 members exceed cutoff -> discarded class slot.
        int cc = (int)__ldg(&pa[PAD * WP2 + PAD]);
        if (cc > 0) votes += 1ull << (3 * cc - 3);
        unsigned long long m = mask;
        while (m) {
            int k = __ffsll((long long)m) - 1;
            m &= m - 1;
            int dy = k / S, dx = k - dy * S;
            int c = (int)__ldg(&pa[dy * WP2 + dx]);
            if (c > 0) votes += 1ull << (3 * c - 3);
        }
    } else {
        // SLOW PATH (~1%): C>=8 candidates -> stable top-7 are the 7 smallest
        // candidates. Key = (f32bits(d) << 6) | k (monotone, lowest-k ties ==
        // jax.lax.top_k stable order). Insertion into 7 sorted regs.
        unsigned long long cand = mask | (1ull << CENTER);
        unsigned long long t0 = ~0ull, t1 = ~0ull, t2 = ~0ull, t3 = ~0ull,
                           t4 = ~0ull, t5 = ~0ull, t6 = ~0ull;
        while (cand) {
            int k = __ffsll((long long)cand) - 1;
            cand &= cand - 1;
            int dy = k / S, dx = k - dy * S;
            float v = (k == CENTER) ? ur : __ldg(&pr[dy * WP2 + dx]);
            float d = fabsf(v - ur) * wp.w[k];
            unsigned long long key =
                ((unsigned long long)__float_as_uint(d) << 6) | (unsigned)k;
            if (key < t6) {
                t6 = key;
                if (t6 < t5) { unsigned long long s = t5; t5 = t6; t6 = s; }
                if (t5 < t4) { unsigned long long s = t4; t4 = t5; t5 = s; }
                if (t4 < t3) { unsigned long long s = t3; t3 = t4; t4 = s; }
                if (t3 < t2) { unsigned long long s = t2; t2 = t3; t3 = s; }
                if (t2 < t1) { unsigned long long s = t1; t1 = t2; t2 = s; }
                if (t1 < t0) { unsigned long long s = t0; t0 = t1; t1 = s; }
            }
        }
        unsigned long long ts[7] = {t0, t1, t2, t3, t4, t5, t6};
#pragma unroll
        for (int j = 0; j < 7; j++) {
            int k = (int)(ts[j] & 63ull);
            int dy = k / S, dx = k - dy * S;
            int c = (int)__ldg(&pa[dy * WP2 + dx]);
            if (c > 0) votes += 1ull << (3 * c - 3);
        }
    }

    // argmax over classes 1..19 (3-bit counters); strict '>' == lowest class
    // wins ties; all-zero -> class 1 (argmax(zeros)+1).
    int best_c = 1, best_n = 0;
#pragma unroll
    for (int c = 1; c <= 19; c++) {
        int n = (int)((votes >> (3 * c - 3)) & 7ull);
        if (n > best_n) { best_n = n; best_c = c; }
    }

    unsigned op = pay.z;
    if (g_roles[5]) ((long long*)outv)[op] = (long long)best_c;
    else            ((float*)outv)[op]     = (float)best_c;
}

extern "C" void kernel_launch(void* const* d_in, const int* in_sizes, int n_in,
                              void* d_out, int out_size) {
    int hw_idx[2], p_idx[3], nh = 0, np_ = 0;
    for (int i = 0; i < n_in; i++) {
        if (in_sizes[i] == HW) { if (nh < 2) hw_idx[nh++] = i; }
        else                   { if (np_ < 3) p_idx[np_++] = i; }
    }
    const void* A0 = d_in[hw_idx[0]];
    const void* A1 = d_in[hw_idx[1]];
    const void* B0 = d_in[p_idx[0]];
    const void* B1 = d_in[p_idx[1]];
    const void* B2 = d_in[p_idx[2]];
    int P = out_size;

    WParams wp;
    {
        const double PI = 3.14159265358979323846;
        double g[K2], sum = 0.0;
        double mean = (S - 1) / 2.0;
        for (int yy = 0; yy < S; yy++)
            for (int xx = 0; xx < S; xx++) {
                double dx = xx - mean, dy = yy - mean;
                double e = exp(-(dx * dx + dy * dy) / 2.0) / (2.0 * PI);
                g[yy * S + xx] = e;
                sum += e;
            }
        for (int k = 0; k < K2; k++) wp.w[k] = (float)(1.0 - g[k] / sum);
    }

    int npix = HP * WP2;
    prep_kernel<<<(npix + 255) / 256, 256>>>(A0, A1, B0, B1, B2);
    hist_kernel<<<(P + 255) / 256, 256>>>(B0, B1, B2, P);
    scan_kernel<<<NCHUNK, 1024>>>();
    scatter_kernel<<<(P + 255) / 256, 256>>>(B0, B1, B2, P);
    knn_kernel<<<(P + 255) / 256, 256>>>(d_out, P, wp);
}